// round 10
// baseline (speedup 1.0000x reference)
#include <cuda_runtime.h>
#include <math.h>
#include <stdint.h>

#define N_TOKENS 65536
#define EMB_DIM  128
#define NUM_EMB  1024

// Output tuple flattened scalar-wise in reference-return order:
// (e_latent_loss, quantized_st[N,D], perplexity, encodings[N,K])
#define OUT_LOSS 0
#define OUT_Q    1
#define OUT_PERP (1 + N_TOKENS * EMB_DIM)        // 8388609
#define OUT_ENC  (2 + N_TOKENS * EMB_DIM)        // 8388610 (even -> 8B-aligned)

#define BM   128
#define NBLK (N_TOKENS / BM)     // 512
#define NTHR 512
#define SAS  132                 // smem tile row stride (int32 words)
#define CAP  16                  // candidates per token

// smem byte offsets (dynamic)
#define SM_A     0        // 16896: A int8 tile as int32 [32 kgroups][132]
#define SM_B     16896    // 16896: B int8 tile
#define SM_RED   33792    // 8192:  float redv[128][16]
#define SM_THR   41984    // 512:   float thr[128]
#define SM_RXS   42496    // 512:   float rxs[128]
#define SM_CNT   43008    // 512:   int   scnt[128]
#define SM_LIST  43520    // 4096:  uint16 slist[128][CAP]
#define SM_SBK   47616    // 512:   int bk[128]
#define SM_LRED  48128    // 4096:  double lred[512]
#define SM_LACC  52224    // 4096:  double lacc[512]
#define DSMEM    56320

__device__ int    g_eq[NUM_EMB * 32];    // int8-packed codebook (k-groups of 4)
__device__ int    g_xq[N_TOKENS * 32];   // int8-packed tokens
__device__ float  g_be[NUM_EMB];         // fl32 of exact ||e_k||^2
__device__ float  g_c2e[NUM_EMB];        // 2*emax_k/127  (dequant*2 factor)
__device__ float  g_sx[N_TOKENS];        // fl32 of exact ||x_n||^2
__device__ float  g_rxs[N_TOKENS];       // amax_n/127 (x dequant factor)
__device__ float  g_s1x[N_TOKENS];       // sum |x_n|
__device__ unsigned g_qe_bits;           // global max qe = emax/254 (float bits)
__device__ unsigned g_s1e_bits;          // global max sum|e_k| (float bits)
__device__ int    g_hist[NUM_EMB];
__device__ double g_lpart[NBLK];
__device__ unsigned int g_done;

// ---------------- warp reduce helpers (fixed order -> deterministic) --------
__device__ __forceinline__ float wmaxf(float v) {
#pragma unroll
    for (int o = 16; o > 0; o >>= 1) v = fmaxf(v, __shfl_down_sync(~0u, v, o));
    return __shfl_sync(~0u, v, 0);
}
__device__ __forceinline__ float wsumf(float v) {
#pragma unroll
    for (int o = 16; o > 0; o >>= 1) v += __shfl_down_sync(~0u, v, o);
    return __shfl_sync(~0u, v, 0);
}
__device__ __forceinline__ double wsumd(double v) {
#pragma unroll
    for (int o = 16; o > 0; o >>= 1) v += __shfl_down_sync(~0u, v, o);
    return v;   // valid on lane 0
}
__device__ __forceinline__ int q8(float v) {
    int q = __float2int_rn(v);
    return q > 127 ? 127 : (q < -127 ? -127 : q);
}

// exact sequential-k fp32 dot (reference accumulation order), float4 loads
__device__ __forceinline__ float exact_dot(const float* __restrict__ xr,
                                           const float* __restrict__ er) {
    const float4* x4 = (const float4*)xr;
    const float4* e4 = (const float4*)er;
    float dot = 0.f;
#pragma unroll 4
    for (int q = 0; q < EMB_DIM / 4; q++) {
        float4 xv = x4[q], ev = e4[q];
        dot = __fmaf_rn(xv.x, ev.x, dot);
        dot = __fmaf_rn(xv.y, ev.y, dot);
        dot = __fmaf_rn(xv.z, ev.z, dot);
        dot = __fmaf_rn(xv.w, ev.w, dot);
    }
    return dot;
}

// ---------------------------------------------------------------------------
__global__ void vq_init_kernel() {
    g_qe_bits = 0u; g_s1e_bits = 0u; g_done = 0u;
}

// prep: per code (warp): norms, abs-max, int8 quantize, global maxima
__global__ void vq_prep_kernel(const float* __restrict__ emb) {
    const int wid = threadIdx.x >> 5, lane = threadIdx.x & 31;
    const int code = blockIdx.x * 8 + wid;
    float4 v = ((const float4*)emb)[code * 32 + lane];
    float am = fmaxf(fmaxf(fabsf(v.x), fabsf(v.y)), fmaxf(fabsf(v.z), fabsf(v.w)));
    float s1 = fabsf(v.x) + fabsf(v.y) + fabsf(v.z) + fabsf(v.w);
    double sd; { double a=v.x,b=v.y,c=v.z,d=v.w; sd = a*a + b*b + c*c + d*d; }
    float emax = fmaxf(wmaxf(am), 1e-30f);
    float s1e  = wsumf(s1);
    double se  = wsumd(sd);
    float ses = 127.0f / emax;
    int pack = (q8(v.x * ses) & 0xff) | ((q8(v.y * ses) & 0xff) << 8)
             | ((q8(v.z * ses) & 0xff) << 16) | ((q8(v.w * ses) & 0xff) << 24);
    g_eq[code * 32 + lane] = pack;
    if (lane == 0) {
        g_be[code]  = (float)se;
        g_c2e[code] = 2.0f * emax / 127.0f;
        g_hist[code] = 0;
        atomicMax(&g_qe_bits, __float_as_uint(emax / 254.0f));
        atomicMax(&g_s1e_bits, __float_as_uint(s1e));
    }
}

// per-token: norms, abs-max, int8 quantize
__global__ void vq_sx_kernel(const float* __restrict__ x) {
    const int wid = threadIdx.x >> 5, lane = threadIdx.x & 31;
    const int row = blockIdx.x * 8 + wid;
    float4 v = ((const float4*)x)[row * 32 + lane];
    float am = fmaxf(fmaxf(fabsf(v.x), fabsf(v.y)), fmaxf(fabsf(v.z), fabsf(v.w)));
    float s1 = fabsf(v.x) + fabsf(v.y) + fabsf(v.z) + fabsf(v.w);
    double sd; { double a=v.x,b=v.y,c=v.z,d=v.w; sd = a*a + b*b + c*c + d*d; }
    float amax = fmaxf(wmaxf(am), 1e-30f);
    float s1x  = wsumf(s1);
    double sx  = wsumd(sd);
    float sxs = 127.0f / amax;
    int pack = (q8(v.x * sxs) & 0xff) | ((q8(v.y * sxs) & 0xff) << 8)
             | ((q8(v.z * sxs) & 0xff) << 16) | ((q8(v.w * sxs) & 0xff) << 24);
    g_xq[row * 32 + lane] = pack;
    if (lane == 0) {
        g_sx[row]  = (float)sx;
        g_rxs[row] = amax / 127.0f;
        g_s1x[row] = s1x;
    }
}

// transpose-load a 128-row x 32-word int8 tile into k-major smem [32][SAS]
// (first 256 threads only)
__device__ __forceinline__ void load_tile(int* dst, const int* __restrict__ gsrc,
                                          int row0, int tid) {
    if (tid < 256) {
        const int lr = tid >> 3, lc = tid & 7;
#pragma unroll
        for (int p = 0; p < 4; p++) {
            int r = p * 32 + lr;
            int4 w = ((const int4*)gsrc)[(size_t)(row0 + r) * 8 + lc];
            dst[(lc * 4 + 0) * SAS + r] = w.x;
            dst[(lc * 4 + 1) * SAS + r] = w.y;
            dst[(lc * 4 + 2) * SAS + r] = w.z;
            dst[(lc * 4 + 3) * SAS + r] = w.w;
        }
    }
}

// ---------------------------------------------------------------------------
// main: two-pass int8 DP4A screening GEMM with a 4x8 per-thread tile
// (512 threads, launch_bounds(512,1) => no register spills), certified-margin
// collection (validated in R9), exact fp32 rescore (R3 bit-identical chain)
// + fused outputs.
// ---------------------------------------------------------------------------
__global__ __launch_bounds__(NTHR, 1)
void vq_main_kernel(const float* __restrict__ x,
                    const float* __restrict__ emb,
                    float* __restrict__ out)
{
    extern __shared__ __align__(16) char dsm[];
    int*       sAq  = (int*)(dsm + SM_A);
    int*       sBq  = (int*)(dsm + SM_B);
    float*     redv = (float*)(dsm + SM_RED);
    float*     sthr = (float*)(dsm + SM_THR);
    float*     srxs = (float*)(dsm + SM_RXS);
    int*       scnt = (int*)(dsm + SM_CNT);
    uint16_t*  slist= (uint16_t*)(dsm + SM_LIST);
    int*       s_bk = (int*)(dsm + SM_SBK);
    double*    lred = (double*)(dsm + SM_LRED);
    double*    lacc = (double*)(dsm + SM_LACC);

    const int tid = threadIdx.x;     // 512
    const int tx  = tid & 15;        // codes tx*8..tx*8+7 within tile
    const int ty  = tid >> 4;        // 0..31 -> tokens ty*4..ty*4+3
    const int m0  = blockIdx.x * BM;

    // ---- zero this block's one-hot rows (big DRAM op, overlaps all) ----
    {
        float2* enc2 = (float2*)(out + OUT_ENC);
        size_t base = (size_t)m0 * (NUM_EMB / 2);
        for (int i = tid; i < BM * NUM_EMB / 2; i += NTHR)
            enc2[base + i] = make_float2(0.f, 0.f);
    }

    // ---- A tile (resident all kernel) + per-token dequant factors ----
    load_tile(sAq, g_xq, m0, tid);
    if (tid < 128) srxs[tid] = g_rxs[m0 + tid];
    __syncthreads();

    // per-thread token dequant factors (registers)
    float rx[4];
#pragma unroll
    for (int i = 0; i < 4; i++) rx[i] = srxs[ty * 4 + i];

    float rmin[4];
#pragma unroll
    for (int i = 0; i < 4; i++) rmin[i] = INFINITY;

    const int* pa = sAq + ty * 4;
    const int* pb = sBq + tx * 8;

    // ================= PASS A: approx min only =================
    for (int ct = 0; ct < 8; ct++) {
        load_tile(sBq, g_eq, ct * 128, tid);
        __syncthreads();
        int acc[4][8];
#pragma unroll
        for (int i = 0; i < 4; i++)
#pragma unroll
            for (int j = 0; j < 8; j++) acc[i][j] = 0;
#pragma unroll 4
        for (int g = 0; g < 32; g++) {
            int4 a4 = *(const int4*)(pa + g * SAS);
            int4 b03 = *(const int4*)(pb + g * SAS);
            int4 b47 = *(const int4*)(pb + g * SAS + 4);
            int aw[4] = {a4.x, a4.y, a4.z, a4.w};
            int bw[8] = {b03.x,b03.y,b03.z,b03.w,b47.x,b47.y,b47.z,b47.w};
#pragma unroll
            for (int i = 0; i < 4; i++)
#pragma unroll
                for (int j = 0; j < 8; j++)
                    acc[i][j] = __dp4a(aw[i], bw[j], acc[i][j]);
        }
#pragma unroll
        for (int j = 0; j < 8; j++) {
            const int k = ct * 128 + tx * 8 + j;
            const float be = __ldg(&g_be[k]);
            const float ce = __ldg(&g_c2e[k]);
#pragma unroll
            for (int i = 0; i < 4; i++) {
                float s = __fmaf_rn(-(float)acc[i][j], __fmul_rn(ce, rx[i]), be);
                rmin[i] = fminf(rmin[i], s);
            }
        }
        __syncthreads();
    }

    // ---- reduce to per-token approx min, build certified thresholds ----
#pragma unroll
    for (int i = 0; i < 4; i++) redv[(ty * 4 + i) * 16 + tx] = rmin[i];
    __syncthreads();
    if (tid < 128) {
        float tm = redv[tid * 16];
#pragma unroll
        for (int t = 1; t < 16; t++) tm = fminf(tm, redv[tid * 16 + t]);
        const float qx  = 0.5f * srxs[tid];
        const float qe  = __uint_as_float(g_qe_bits);
        const float s1e = __uint_as_float(g_s1e_bits);
        const float s1x = g_s1x[m0 + tid];
        const float delta = 4.0f * (s1x * qe + qx * s1e + 128.0f * qx * qe) + 6e-5f;
        sthr[tid] = tm + delta;
        scnt[tid] = 0;
    }
    __syncthreads();

    // per-thread thresholds (registers)
    float thr[4];
#pragma unroll
    for (int i = 0; i < 4; i++) thr[i] = sthr[ty * 4 + i];

    // ================= PASS B: collect candidates =================
    for (int ct = 0; ct < 8; ct++) {
        load_tile(sBq, g_eq, ct * 128, tid);
        __syncthreads();
        int acc[4][8];
#pragma unroll
        for (int i = 0; i < 4; i++)
#pragma unroll
            for (int j = 0; j < 8; j++) acc[i][j] = 0;
#pragma unroll 4
        for (int g = 0; g < 32; g++) {
            int4 a4 = *(const int4*)(pa + g * SAS);
            int4 b03 = *(const int4*)(pb + g * SAS);
            int4 b47 = *(const int4*)(pb + g * SAS + 4);
            int aw[4] = {a4.x, a4.y, a4.z, a4.w};
            int bw[8] = {b03.x,b03.y,b03.z,b03.w,b47.x,b47.y,b47.z,b47.w};
#pragma unroll
            for (int i = 0; i < 4; i++)
#pragma unroll
                for (int j = 0; j < 8; j++)
                    acc[i][j] = __dp4a(aw[i], bw[j], acc[i][j]);
        }
#pragma unroll
        for (int j = 0; j < 8; j++) {
            const int k = ct * 128 + tx * 8 + j;
            const float be = __ldg(&g_be[k]);
            const float ce = __ldg(&g_c2e[k]);
#pragma unroll
            for (int i = 0; i < 4; i++) {
                float s = __fmaf_rn(-(float)acc[i][j], __fmul_rn(ce, rx[i]), be);
                if (s <= thr[i]) {
                    int idx = atomicAdd(&scnt[ty * 4 + i], 1);
                    if (idx < CAP) slist[(ty * 4 + i) * CAP + idx] = (uint16_t)k;
                }
            }
        }
        __syncthreads();
    }

    // ---- phase 2: exact rescore (R3 bit-exact arithmetic) ----
    if (tid < 128) {
        const int row = m0 + tid;
        const float sxe = g_sx[row];
        const float* xr = x + (size_t)row * EMB_DIM;
        float bv = INFINITY;
        int   bk = 1 << 30;
        const int nc = scnt[tid];
        if (nc > CAP) {
            // certified-margin overflow fallback (P ~ 1e-7): full exact scan
            for (int k = 0; k < NUM_EMB; k++) {
                float dot = exact_dot(xr, emb + (size_t)k * EMB_DIM);
                float d = __fsub_rn(__fadd_rn(sxe, g_be[k]),
                                    __fmul_rn(2.0f, dot));
                if (d < bv || (d == bv && k < bk)) { bv = d; bk = k; }
            }
        } else {
            for (int i = 0; i < nc; i++) {
                const int k = slist[tid * CAP + i];
                float dot = exact_dot(xr, emb + (size_t)k * EMB_DIM);
                float d = __fsub_rn(__fadd_rn(sxe, g_be[k]),
                                    __fmul_rn(2.0f, dot));
                if (d < bv || (d == bv && k < bk)) { bv = d; bk = k; }
            }
        }
        s_bk[tid] = bk;
        out[(size_t)OUT_ENC + (size_t)row * NUM_EMB + bk] = 1.0f;
        atomicAdd(&g_hist[bk], 1);   // integer atomic: deterministic
    }
    __syncthreads();

    // ---- cooperative coalesced quantized_st + loss (32-bit stores) ----
    double lsum = 0.0;
    float* oq = out + OUT_Q + (size_t)m0 * EMB_DIM;
    const float* xq = x + (size_t)m0 * EMB_DIM;
    for (int e = tid; e < BM * EMB_DIM; e += NTHR) {
        const int row = e >> 7;
        const int col = e & 127;
        const float xv = xq[e];
        const float qv = emb[(size_t)s_bk[row] * EMB_DIM + col];
        const float d  = __fsub_rn(qv, xv);
        oq[e] = __fadd_rn(xv, d);        // fl(x + fl(q-x)), exact STE math
        lsum += (double)d * (double)d;
    }
    lred[tid] = lsum;
    __syncthreads();
    for (int s = NTHR / 2; s > 0; s >>= 1) {
        if (tid < s) lred[tid] += lred[tid + s];
        __syncthreads();
    }
    if (tid == 0) g_lpart[blockIdx.x] = lred[0];

    // ---- last block computes the scalars (fused finalize) ----
    __shared__ bool is_last;
    __threadfence();
    if (tid == 0) {
        unsigned v = atomicAdd(&g_done, 1u);
        is_last = (v == NBLK - 1);
    }
    __syncthreads();
    if (!is_last) return;

    double ent = 0.0;
#pragma unroll
    for (int b = 0; b < 2; b++) {
        double pr = (double)g_hist[tid * 2 + b] / (double)N_TOKENS;
        ent += pr * log(pr + 1e-10);
    }
    double ls = g_lpart[tid];          // NBLK == NTHR == 512
    lred[tid] = ent;
    lacc[tid] = ls;
    __syncthreads();
    for (int s = NTHR / 2; s > 0; s >>= 1) {
        if (tid < s) { lred[tid] += lred[tid + s]; lacc[tid] += lacc[tid + s]; }
        __syncthreads();
    }
    if (tid == 0) {
        out[OUT_PERP] = (float)exp(-lred[0]);
        out[OUT_LOSS] = (float)(lacc[0] / ((double)N_TOKENS * (double)EMB_DIM));
    }
}

// ---------------------------------------------------------------------------
extern "C" void kernel_launch(void* const* d_in, const int* in_sizes, int n_in,
                              void* d_out, int out_size) {
    const float* x   = (const float*)d_in[0];   // inputs [65536,128]
    const float* emb = (const float*)d_in[1];   // emb_w  [1024,128]
    float* out = (float*)d_out;

    cudaFuncSetAttribute(vq_main_kernel,
                         cudaFuncAttributeMaxDynamicSharedMemorySize, DSMEM);
    vq_init_kernel<<<1, 1>>>();
    vq_prep_kernel<<<NUM_EMB / 8, 256>>>(emb);
    vq_sx_kernel<<<N_TOKENS / 8, 256>>>(x);
    vq_main_kernel<<<NBLK, NTHR, DSMEM>>>(x, emb, out);
}

// round 11
// speedup vs baseline: 3.6559x; 3.6559x over previous
#include <cuda_runtime.h>
#include <math.h>
#include <stdint.h>

#define N_TOKENS 65536
#define EMB_DIM  128
#define NUM_EMB  1024

// Output tuple flattened scalar-wise in reference-return order:
// (e_latent_loss, quantized_st[N,D], perplexity, encodings[N,K])
#define OUT_LOSS 0
#define OUT_Q    1
#define OUT_PERP (1 + N_TOKENS * EMB_DIM)        // 8388609
#define OUT_ENC  (2 + N_TOKENS * EMB_DIM)        // 8388610 (even -> 8B-aligned)

#define BM   128
#define NBLK (N_TOKENS / BM)     // 512
#define SAS  132                 // A tile: float stride per k-row (conflict-free)
#define SBD  130                 // B tile: u64 stride per k-row (dup'd codes)

// dynamic smem layout (bytes)
#define SM_A     0               // 32*132*4 = 16896
#define SM_B     16896           // 32*130*8 = 33280  -> GEMM total 50176
// post-GEMM reuse (after __syncthreads):
#define SM_REDV  0               // 8192: float redv[128][16]
#define SM_REDI  8192            // 8192: int   redi[128][16]
#define SM_SBK   16384           // 512:  int bk[128]
#define SM_LRED  16896           // 2048: double lred[256]
#define SM_LACC  18944           // 2048: double lacc[256]
#define DSMEM    50176

typedef unsigned long long u64;

__device__ float  g_be[NUM_EMB];     // fl32 of exact ||e_k||^2
__device__ float  g_sx[N_TOKENS];    // fl32 of exact ||x_n||^2
__device__ int    g_hist[NUM_EMB];   // code counts
__device__ double g_lpart[NBLK];     // per-block loss partials
__device__ unsigned int g_done;      // last-block-done counter

// packed f32x2 FMA: two independent exact fp32 RN FMAs per instruction
__device__ __forceinline__ u64 ffma2(u64 a, u64 b, u64 c) {
    u64 d;
    asm("fma.rn.f32x2 %0, %1, %2, %3;" : "=l"(d) : "l"(a), "l"(b), "l"(c));
    return d;
}
__device__ __forceinline__ void unpack2(u64 v, float& lo, float& hi) {
    asm("mov.b64 {%0, %1}, %2;" : "=f"(lo), "=f"(hi) : "l"(v));
}
__device__ __forceinline__ double wsumd(double v) {
#pragma unroll
    for (int o = 16; o > 0; o >>= 1) v += __shfl_down_sync(~0u, v, o);
    return v;   // valid on lane 0
}

// ---------------------------------------------------------------------------
// prep: codebook squared norms (double, order-insensitive) + zero hist/done
// ---------------------------------------------------------------------------
__global__ void vq_prep_kernel(const float* __restrict__ emb) {
    const int gtid = blockIdx.x * 256 + threadIdx.x;   // 32768 threads
    const int code = gtid >> 5, lane = gtid & 31;
    float4 v = ((const float4*)emb)[code * 32 + lane];
    double s;
    { double a = v.x, b = v.y, c = v.z, d = v.w; s = a*a + b*b + c*c + d*d; }
    s = wsumd(s);
    if (lane == 0) { g_be[code] = (float)s; g_hist[code] = 0; }
    if (gtid == 0) g_done = 0;
}

// per-token squared norms, double accumulation (order-insensitive)
__global__ void vq_sx_kernel(const float* __restrict__ x) {
    const int gtid = blockIdx.x * 256 + threadIdx.x;
    const int row = gtid >> 5, lane = gtid & 31;
    float4 v = ((const float4*)x)[row * 32 + lane];
    double s;
    { double a = v.x, b = v.y, c = v.z, d = v.w; s = a*a + b*b + c*c + d*d; }
    s = wsumd(s);
    if (lane == 0) g_sx[row] = (float)s;
}

// ---------------------------------------------------------------------------
// main: FFMA2-packed exact fp32 tiled GEMM (x @ emb^T). Each (token,code) dot
// is a strict sequential fp32 FMA chain over k ascending (one f32x2 lane) —
// bit-identical to the reference. Distance uses reference rounding exactly:
//   d = fl( fl(sx + be_k) - fl(2*dot) )
// B tile lane-duplicated in smem (strided ownership: conflict-free LDS.64).
// Fused epilogue: argmin, one-hot, histogram, quantized_st, loss, scalars.
// ---------------------------------------------------------------------------
__global__ __launch_bounds__(256, 2)
void vq_main_kernel(const float* __restrict__ x,
                    const float* __restrict__ emb,
                    float* __restrict__ out)
{
    extern __shared__ __align__(16) char dsm[];
    float* sA = (float*)(dsm + SM_A);     // [32][SAS] floats, k-major
    u64*   sB = (u64*)(dsm + SM_B);       // [32][SBD] u64 (code value dup'd)

    const int tid = threadIdx.x;          // 256
    const int tx  = tid & 15;             // codes tx + 16j (strided)
    const int ty  = tid >> 4;             // tokens ty*8 .. ty*8+7 (4 pairs)
    const int m0  = blockIdx.x * BM;

    const int lr = tid >> 3;              // 0..31 : loader row
    const int lc = tid & 7;               // 0..7  : loader float4 column

    // ---- zero this block's one-hot rows (big DRAM op, overlaps GEMM) ----
    {
        float2* enc2 = (float2*)(out + OUT_ENC);
        size_t base = (size_t)m0 * (NUM_EMB / 2);
        for (int i = tid; i < BM * NUM_EMB / 2; i += 256)
            enc2[base + i] = make_float2(0.f, 0.f);
    }

    const float4* x4 = (const float4*)x;
    const float4* e4 = (const float4*)emb;

    // per-thread token norms: token = ty*8 + 2p + q
    float sxr[4][2];
#pragma unroll
    for (int p = 0; p < 4; p++) {
        sxr[p][0] = g_sx[m0 + ty * 8 + 2 * p + 0];
        sxr[p][1] = g_sx[m0 + ty * 8 + 2 * p + 1];
    }

    float rmin[4][2];
    int   ridx[4][2];
#pragma unroll
    for (int p = 0; p < 4; p++)
#pragma unroll
        for (int q = 0; q < 2; q++) { rmin[p][q] = INFINITY; ridx[p][q] = 0; }

    for (int ct = 0; ct < NUM_EMB / 128; ct++) {      // 8 code tiles
        u64 acc[4][8];
#pragma unroll
        for (int p = 0; p < 4; p++)
#pragma unroll
            for (int j = 0; j < 8; j++) acc[p][j] = 0ull;

        for (int ks = 0; ks < 4; ks++) {              // 4 depth steps, ascending
            __syncthreads();
#pragma unroll
            for (int p = 0; p < 4; p++) {
                int r = p * 32 + lr;
                float4 va = x4[(size_t)(m0 + r) * 32 + ks * 8 + lc];
                float4 vb = e4[(size_t)(ct * 128 + r) * 32 + ks * 8 + lc];
                int kk = lc * 4;
                sA[(kk + 0) * SAS + r] = va.x;
                sA[(kk + 1) * SAS + r] = va.y;
                sA[(kk + 2) * SAS + r] = va.z;
                sA[(kk + 3) * SAS + r] = va.w;
                *(float2*)&sB[(kk + 0) * SBD + r] = make_float2(vb.x, vb.x);
                *(float2*)&sB[(kk + 1) * SBD + r] = make_float2(vb.y, vb.y);
                *(float2*)&sB[(kk + 2) * SBD + r] = make_float2(vb.z, vb.z);
                *(float2*)&sB[(kk + 3) * SBD + r] = make_float2(vb.w, vb.w);
            }
            __syncthreads();

#pragma unroll
            for (int k = 0; k < 32; k++) {            // ascending k per acc
                const float* ar = sA + k * SAS + ty * 8;
                ulonglong2 aA = *(const ulonglong2*)ar;        // tokens 0..3
                ulonglong2 aB = *(const ulonglong2*)(ar + 4);  // tokens 4..7
                const u64* br = sB + k * SBD;
#pragma unroll
                for (int j = 0; j < 8; j++) {
                    u64 b = br[tx + 16 * j];          // conflict-free LDS.64
                    acc[0][j] = ffma2(aA.x, b, acc[0][j]);
                    acc[1][j] = ffma2(aA.y, b, acc[1][j]);
                    acc[2][j] = ffma2(aB.x, b, acc[2][j]);
                    acc[3][j] = ffma2(aB.y, b, acc[3][j]);
                }
            }
        }

        // fold distances with reference rounding; j ascending => kk ascending
#pragma unroll
        for (int j = 0; j < 8; j++) {
            const int kk  = ct * 128 + tx + 16 * j;
            const float bek = g_be[kk];
#pragma unroll
            for (int p = 0; p < 4; p++) {
                float lo, hi;
                unpack2(acc[p][j], lo, hi);
                float d0 = __fsub_rn(__fadd_rn(sxr[p][0], bek),
                                     __fmul_rn(2.0f, lo));
                float d1 = __fsub_rn(__fadd_rn(sxr[p][1], bek),
                                     __fmul_rn(2.0f, hi));
                if (d0 < rmin[p][0]) { rmin[p][0] = d0; ridx[p][0] = kk; }
                if (d1 < rmin[p][1]) { rmin[p][1] = d1; ridx[p][1] = kk; }
            }
        }
    }

    // -------- cross-thread argmin reduction (16 tx-threads per token) ------
    __syncthreads();
    float*  redv = (float*)(dsm + SM_REDV);
    int*    redi = (int*)(dsm + SM_REDI);
    int*    s_bk = (int*)(dsm + SM_SBK);
    double* lred = (double*)(dsm + SM_LRED);
    double* lacc = (double*)(dsm + SM_LACC);
#pragma unroll
    for (int p = 0; p < 4; p++)
#pragma unroll
        for (int q = 0; q < 2; q++) {
            const int t = ty * 8 + 2 * p + q;
            redv[t * 16 + tx] = rmin[p][q];
            redi[t * 16 + tx] = ridx[p][q];
        }
    __syncthreads();

    if (tid < 128) {
        float bv = redv[tid * 16];
        int   bk = redi[tid * 16];
#pragma unroll
        for (int t = 1; t < 16; t++) {
            float v  = redv[tid * 16 + t];
            int   kk = redi[tid * 16 + t];
            if (v < bv || (v == bv && kk < bk)) { bv = v; bk = kk; }
        }
        s_bk[tid] = bk;
        const int row = m0 + tid;
        out[(size_t)OUT_ENC + (size_t)row * NUM_EMB + bk] = 1.0f;
        atomicAdd(&g_hist[bk], 1);   // integer atomic: deterministic
    }
    __syncthreads();

    // -------- cooperative coalesced quantized_st + loss (32-bit stores) ----
    double lsum = 0.0;
    float* oq = out + OUT_Q + (size_t)m0 * EMB_DIM;
    const float* xq = x + (size_t)m0 * EMB_DIM;
    for (int e = tid; e < BM * EMB_DIM; e += 256) {
        const int row = e >> 7;
        const int col = e & 127;
        const float xv = xq[e];
        const float qv = emb[(size_t)s_bk[row] * EMB_DIM + col];
        const float d  = __fsub_rn(qv, xv);
        oq[e] = __fadd_rn(xv, d);        // fl(x + fl(q-x)), exact STE math
        lsum += (double)d * (double)d;
    }
    lred[tid] = lsum;
    __syncthreads();
    for (int s = 128; s > 0; s >>= 1) {
        if (tid < s) lred[tid] += lred[tid + s];
        __syncthreads();
    }
    if (tid == 0) g_lpart[blockIdx.x] = lred[0];

    // -------- last block computes the scalars (fused finalize) --------
    __shared__ bool is_last;
    __threadfence();
    if (tid == 0) {
        unsigned v = atomicAdd(&g_done, 1u);
        is_last = (v == NBLK - 1);
    }
    __syncthreads();
    if (!is_last) return;

    double ent = 0.0;
#pragma unroll
    for (int b = 0; b < 4; b++) {
        double pr = (double)g_hist[tid * 4 + b] / (double)N_TOKENS;
        ent += pr * log(pr + 1e-10);
    }
    double ls = 0.0;
#pragma unroll
    for (int b = 0; b < 2; b++) ls += g_lpart[tid * 2 + b];
    lred[tid] = ent;
    lacc[tid] = ls;
    __syncthreads();
    for (int s = 128; s > 0; s >>= 1) {
        if (tid < s) { lred[tid] += lred[tid + s]; lacc[tid] += lacc[tid + s]; }
        __syncthreads();
    }
    if (tid == 0) {
        out[OUT_PERP] = (float)exp(-lred[0]);
        out[OUT_LOSS] = (float)(lacc[0] / ((double)N_TOKENS * (double)EMB_DIM));
    }
}

// ---------------------------------------------------------------------------
extern "C" void kernel_launch(void* const* d_in, const int* in_sizes, int n_in,
                              void* d_out, int out_size) {
    const float* x   = (const float*)d_in[0];   // inputs [65536,128]
    const float* emb = (const float*)d_in[1];   // emb_w  [1024,128]
    float* out = (float*)d_out;

    cudaFuncSetAttribute(vq_main_kernel,
                         cudaFuncAttributeMaxDynamicSharedMemorySize, DSMEM);
    vq_prep_kernel<<<NUM_EMB * 32 / 256, 256>>>(emb);
    vq_sx_kernel<<<N_TOKENS * 32 / 256, 256>>>(x);
    vq_main_kernel<<<NBLK, 256, DSMEM>>>(x, emb, out);
}

// round 13
// speedup vs baseline: 4.1173x; 1.1262x over previous
#include <cuda_runtime.h>
#include <cuda_fp16.h>
#include <math.h>
#include <stdint.h>

#define N_TOKENS 65536
#define EMB_DIM  128
#define NUM_EMB  1024

// Output tuple flattened scalar-wise in reference-return order:
// (e_latent_loss, quantized_st[N,D], perplexity, encodings[N,K])
#define OUT_LOSS 0
#define OUT_Q    1
#define OUT_PERP (1 + N_TOKENS * EMB_DIM)        // 8388609
#define OUT_ENC  (2 + N_TOKENS * EMB_DIM)        // 8388610 (even -> 8B-aligned)

#define BM   128
#define NBLK (N_TOKENS / BM)     // 512
#define CAP  32                  // candidate list capacity per token

#define APAD 68                  // A tile: half2 stride per k-row
#define BPAD 132                 // B tile: half2 stride per k-row (dup'd codes)

// dynamic smem layout (bytes)
#define SM_A    0                // 128*68*4  = 34816 : A fp16 [k][tokenpair]
#define SM_B    34816            // 32*132*4  = 16896 : B fp16 dup'd [k][code]
#define SM_RED  51712            // 8192 : float redv[128][16]
#define SM_SMIN 59904            // 512  : float smin[128] (running min)
#define SM_STHR 60416            // 512  : float sthr[128] (smin + delta)
#define SM_CNT  60928            // 512  : int scnt[128]
#define SM_LIST 61440            // 8192 : uint16 slist[128][CAP]
#define DSMEM   69632
// epilogue reuse inside SM_A (after screening sync):
#define SM2_SBK  0               // 512 : int bk[128]
#define SM2_LRED 512             // 2048: double lred[256]
#define SM2_LACC 2560            // 2048: double lacc[256]

__device__ __align__(16) __half g_ehalfT[EMB_DIM * NUM_EMB]; // [k][code], e*1024
__device__ float  g_be[NUM_EMB];     // fl32 of exact ||e_k||^2
__device__ float  g_sx[N_TOKENS];    // fl32 of exact ||x_n||^2
__device__ int    g_hist[NUM_EMB];   // code counts
__device__ double g_lpart[NBLK];     // per-block loss partials
__device__ unsigned int g_done;      // last-block-done counter

__device__ __forceinline__ double wsumd(double v) {
#pragma unroll
    for (int o = 16; o > 0; o >>= 1) v += __shfl_down_sync(~0u, v, o);
    return v;   // valid on lane 0
}

// exact sequential-k fp32 dot (reference accumulation order), float4 loads
__device__ __forceinline__ float exact_dot(const float* __restrict__ xr,
                                           const float* __restrict__ er) {
    const float4* x4 = (const float4*)xr;
    const float4* e4 = (const float4*)er;
    float dot = 0.f;
#pragma unroll 4
    for (int q = 0; q < EMB_DIM / 4; q++) {
        float4 xv = x4[q], ev = e4[q];
        dot = __fmaf_rn(xv.x, ev.x, dot);
        dot = __fmaf_rn(xv.y, ev.y, dot);
        dot = __fmaf_rn(xv.z, ev.z, dot);
        dot = __fmaf_rn(xv.w, ev.w, dot);
    }
    return dot;
}

// ---------------------------------------------------------------------------
// prep: exact double code norms; transposed fp16 codebook scaled by 1024
// (keeps values out of fp16 subnormals); zero hist/done. Warp per code.
// ---------------------------------------------------------------------------
__global__ void vq_prep_kernel(const float* __restrict__ emb) {
    const int gtid = blockIdx.x * 256 + threadIdx.x;   // 32768 threads
    const int code = gtid >> 5, lane = gtid & 31;
    float4 v = ((const float4*)emb)[code * 32 + lane];
    double s;
    { double a = v.x, b = v.y, c = v.z, d = v.w; s = a*a + b*b + c*c + d*d; }
    float arr[4] = {v.x, v.y, v.z, v.w};
#pragma unroll
    for (int i = 0; i < 4; i++)
        g_ehalfT[(size_t)(lane * 4 + i) * NUM_EMB + code] =
            __float2half_rn(arr[i] * 1024.0f);
    s = wsumd(s);
    if (lane == 0) { g_be[code] = (float)s; g_hist[code] = 0; }
    if (gtid == 0) g_done = 0;
}

// per-token squared norms, double accumulation (order-insensitive)
__global__ void vq_sx_kernel(const float* __restrict__ x) {
    const int gtid = blockIdx.x * 256 + threadIdx.x;
    const int row = gtid >> 5, lane = gtid & 31;
    float4 v = ((const float4*)x)[row * 32 + lane];
    double s;
    { double a = v.x, b = v.y, c = v.z, d = v.w; s = a*a + b*b + c*c + d*d; }
    s = wsumd(s);
    if (lane == 0) g_sx[row] = (float)s;
}

// ---------------------------------------------------------------------------
// main: fp16 HFMA2 screening GEMM; per-tile deterministic smem min-merge +
// margin insert (no atomicMin, no volatile); exact fp32 rescore (R3 bit-exact
// chain) + fused outputs.
// ---------------------------------------------------------------------------
__global__ __launch_bounds__(256, 2)
void vq_main_kernel(const float* __restrict__ x,
                    const float* __restrict__ emb,
                    float* __restrict__ out)
{
    extern __shared__ __align__(16) char dsm[];
    float*     redv  = (float*)(dsm + SM_RED);
    float*     smin  = (float*)(dsm + SM_SMIN);
    float*     sthr  = (float*)(dsm + SM_STHR);
    int*       scnt  = (int*)(dsm + SM_CNT);
    uint16_t*  slist = (uint16_t*)(dsm + SM_LIST);

    const int tid = threadIdx.x;          // 256
    const int tx  = tid & 15;             // codes tx + 16j (strided, cf-free)
    const int ty  = tid >> 4;             // token pairs ty*4 .. ty*4+3
    const int m0  = blockIdx.x * BM;

    // ---- zero this block's one-hot rows (big DRAM op, overlaps GEMM) ----
    {
        float2* enc2 = (float2*)(out + OUT_ENC);
        size_t base = (size_t)m0 * (NUM_EMB / 2);
        for (int i = tid; i < BM * NUM_EMB / 2; i += 256)
            enc2[base + i] = make_float2(0.f, 0.f);
    }

    // ---- A tile: x -> fp16, [k][tokenpair] half2 layout ----
    {
        const int t = tid >> 1, kh = tid & 1;
        const float4* xr = (const float4*)(x + (size_t)(m0 + t) * EMB_DIM)
                           + kh * 16;
        const int pair = t >> 1, ln = t & 1;
#pragma unroll 4
        for (int c = 0; c < 16; c++) {
            float4 v = xr[c];
            const int k = kh * 64 + c * 4;
            float arr[4] = {v.x, v.y, v.z, v.w};
#pragma unroll
            for (int i = 0; i < 4; i++)
                *(__half*)(dsm + SM_A + (size_t)((k + i) * APAD + pair) * 4
                           + ln * 2) = __float2half_rn(arr[i]);
        }
    }
    // per-token state init + margin (scales with token norm; >=75 sigma)
    float mydelta = 0.f;
    if (tid < 128) {
        smin[tid] = INFINITY;
        scnt[tid] = 0;
        const float sx = g_sx[m0 + tid];
        mydelta = 2e-3f * fmaxf(1.0f, sqrtf(sx * 0.0078125f));
    }

    // ---- screening: 8 code tiles x 4 k-stages; HFMA2 inner loop ----
    half2 acc[4][8];
    for (int ct = 0; ct < 8; ct++) {
#pragma unroll
        for (int p = 0; p < 4; p++)
#pragma unroll
            for (int j = 0; j < 8; j++)
                acc[p][j] = __half2half2(__ushort_as_half((unsigned short)0));

        for (int ks = 0; ks < 4; ks++) {
            __syncthreads();
            // stage B chunk: g_ehalfT[k][code] -> dup'd half2 smem [k][code]
            {
                const __half* Esrc = g_ehalfT
                    + (size_t)(ks * 32) * NUM_EMB + ct * 128;
#pragma unroll
                for (int r = 0; r < 8; r++) {
                    const int idx = r * 256 + tid;
                    const int c2 = idx & 63;       // code pair
                    const int k  = idx >> 6;       // 0..31
                    unsigned u = *(const unsigned*)(Esrc
                        + (size_t)k * NUM_EMB + c2 * 2);
                    half2 dlo = __half2half2(
                        __ushort_as_half((unsigned short)(u & 0xffffu)));
                    half2 dhi = __half2half2(
                        __ushort_as_half((unsigned short)(u >> 16)));
                    uint2 w;
                    w.x = *(unsigned*)&dlo; w.y = *(unsigned*)&dhi;
                    *(uint2*)(dsm + SM_B + (size_t)(k * BPAD + c2 * 2) * 4) = w;
                }
            }
            __syncthreads();

#pragma unroll 4
            for (int k = 0; k < 32; k++) {
                const int kg = ks * 32 + k;
                uint4 av = *(const uint4*)(dsm + SM_A
                    + (size_t)(kg * APAD + ty * 4) * 4);
                half2 a0 = *(half2*)&av.x, a1 = *(half2*)&av.y;
                half2 a2 = *(half2*)&av.z, a3 = *(half2*)&av.w;
                const half2* br = (const half2*)(dsm + SM_B) + k * BPAD;
#pragma unroll
                for (int j = 0; j < 8; j++) {
                    half2 b = br[tx + 16 * j];     // conflict-free LDS.32
                    acc[0][j] = __hfma2(a0, b, acc[0][j]);
                    acc[1][j] = __hfma2(a1, b, acc[1][j]);
                    acc[2][j] = __hfma2(a2, b, acc[2][j]);
                    acc[3][j] = __hfma2(a3, b, acc[3][j]);
                }
            }
        }

        // ---- fold 1: per-thread tile-min per token -> smem ----
        float tmin[4][2];
#pragma unroll
        for (int p = 0; p < 4; p++) { tmin[p][0] = INFINITY; tmin[p][1] = INFINITY; }
#pragma unroll
        for (int j = 0; j < 8; j++) {
            const int kk = ct * 128 + tx + 16 * j;
            const float be = __ldg(&g_be[kk]);
#pragma unroll
            for (int p = 0; p < 4; p++) {
                float2 df = __half22float2(acc[p][j]);
                // s = be - 2*dot = be - (2/1024)*dot'   (exact pow2 scale)
                tmin[p][0] = fminf(tmin[p][0], __fmaf_rn(-0.001953125f, df.x, be));
                tmin[p][1] = fminf(tmin[p][1], __fmaf_rn(-0.001953125f, df.y, be));
            }
        }
#pragma unroll
        for (int p = 0; p < 4; p++) {
            redv[(ty * 8 + 2 * p + 0) * 16 + tx] = tmin[p][0];
            redv[(ty * 8 + 2 * p + 1) * 16 + tx] = tmin[p][1];
        }
        __syncthreads();

        // ---- merge: running min + threshold (fixed order, deterministic) --
        if (tid < 128) {
            float m = smin[tid];
#pragma unroll
            for (int t = 0; t < 16; t++) m = fminf(m, redv[tid * 16 + t]);
            smin[tid] = m;
            sthr[tid] = m + mydelta;
        }
        __syncthreads();

        // ---- fold 2: insert codes within margin of min-so-far ----
#pragma unroll
        for (int j = 0; j < 8; j++) {
            const int kk = ct * 128 + tx + 16 * j;
            const float be = __ldg(&g_be[kk]);
#pragma unroll
            for (int p = 0; p < 4; p++) {
                float2 df = __half22float2(acc[p][j]);
                const int t0 = ty * 8 + 2 * p;
                float s0 = __fmaf_rn(-0.001953125f, df.x, be);
                float s1 = __fmaf_rn(-0.001953125f, df.y, be);
                if (s0 <= sthr[t0]) {
                    int i = atomicAdd(scnt + t0, 1);
                    if (i < CAP) slist[t0 * CAP + i] = (uint16_t)kk;
                }
                if (s1 <= sthr[t0 + 1]) {
                    int i = atomicAdd(scnt + t0 + 1, 1);
                    if (i < CAP) slist[(t0 + 1) * CAP + i] = (uint16_t)kk;
                }
            }
        }
        __syncthreads();   // inserts + redv reads done before next tile
    }

    // ---- phase 2: exact rescore (R3 bit-exact arithmetic) ----
    int*    s_bk = (int*)(dsm + SM2_SBK);
    double* lred = (double*)(dsm + SM2_LRED);
    double* lacc = (double*)(dsm + SM2_LACC);
    if (tid < 128) {
        const int row = m0 + tid;
        const float sxe = g_sx[row];
        const float* xr = x + (size_t)row * EMB_DIM;
        float bv = INFINITY;
        int   bk = NUM_EMB;    // safe sentinel (never used as index below)
        const int nc = scnt[tid];
        if (nc <= 0 || nc > CAP) {
            // safety fallback: full exact scan (nc>=1 is structural)
            for (int k = 0; k < NUM_EMB; k++) {
                float dot = exact_dot(xr, emb + (size_t)k * EMB_DIM);
                float d = __fsub_rn(__fadd_rn(sxe, g_be[k]),
                                    __fmul_rn(2.0f, dot));
                if (d < bv || (d == bv && k < bk)) { bv = d; bk = k; }
            }
        } else {
            // min over candidate set: order-independent -> deterministic
            for (int i = 0; i < nc; i++) {
                const int k = slist[tid * CAP + i];
                float dot = exact_dot(xr, emb + (size_t)k * EMB_DIM);
                float d = __fsub_rn(__fadd_rn(sxe, g_be[k]),
                                    __fmul_rn(2.0f, dot));
                if (d < bv || (d == bv && k < bk)) { bv = d; bk = k; }
            }
        }
        s_bk[tid] = bk;
        out[(size_t)OUT_ENC + (size_t)row * NUM_EMB + bk] = 1.0f;
        atomicAdd(&g_hist[bk], 1);   // integer atomic: deterministic
    }
    __syncthreads();

    // ---- cooperative coalesced quantized_st + loss (32-bit stores) ----
    double lsum = 0.0;
    float* oq = out + OUT_Q + (size_t)m0 * EMB_DIM;
    const float* xq = x + (size_t)m0 * EMB_DIM;
    for (int e = tid; e < BM * EMB_DIM; e += 256) {
        const int row = e >> 7;
        const int col = e & 127;
        const float xv = xq[e];
        const float qv = emb[(size_t)s_bk[row] * EMB_DIM + col];
        const float d  = __fsub_rn(qv, xv);
        oq[e] = __fadd_rn(xv, d);        // fl(x + fl(q-x)), exact STE math
        lsum += (double)d * (double)d;
    }
    lred[tid] = lsum;
    __syncthreads();
    for (int s = 128; s > 0; s >>= 1) {
        if (tid < s) lred[tid] += lred[tid + s];
        __syncthreads();
    }
    if (tid == 0) g_lpart[blockIdx.x] = lred[0];

    // ---- last block computes the scalars (fused finalize) ----
    __shared__ bool is_last;
    __threadfence();
    if (tid == 0) {
        unsigned v = atomicAdd(&g_done, 1u);
        is_last = (v == NBLK - 1);
    }
    __syncthreads();
    if (!is_last) return;

    double ent = 0.0;
#pragma unroll
    for (int b = 0; b < 4; b++) {
        double pr = (double)g_hist[tid * 4 + b] / (double)N_TOKENS;
        ent += pr * log(pr + 1e-10);
    }
    double ls = 0.0;
#pragma unroll
    for (int b = 0; b < 2; b++) ls += g_lpart[tid * 2 + b];
    lred[tid] = ent;
    lacc[tid] = ls;
    __syncthreads();
    for (int s = 128; s > 0; s >>= 1) {
        if (tid < s) { lred[tid] += lred[tid + s]; lacc[tid] += lacc[tid + s]; }
        __syncthreads();
    }
    if (tid == 0) {
        out[OUT_PERP] = (float)exp(-lred[0]);
        out[OUT_LOSS] = (float)(lacc[0] / ((double)N_TOKENS * (double)EMB_DIM));
    }
}

// ---------------------------------------------------------------------------
extern "C" void kernel_launch(void* const* d_in, const int* in_sizes, int n_in,
                              void* d_out, int out_size) {
    const float* x   = (const float*)d_in[0];   // inputs [65536,128]
    const float* emb = (const float*)d_in[1];   // emb_w  [1024,128]
    float* out = (float*)d_out;

    cudaFuncSetAttribute(vq_main_kernel,
                         cudaFuncAttributeMaxDynamicSharedMemorySize, DSMEM);
    vq_prep_kernel<<<NUM_EMB * 32 / 256, 256>>>(emb);
    vq_sx_kernel<<<N_TOKENS * 32 / 256, 256>>>(x);
    vq_main_kernel<<<NBLK, 256, DSMEM>>>(x, emb, out);
}

// round 14
// speedup vs baseline: 4.6242x; 1.1231x over previous
#include <cuda_runtime.h>
#include <cuda_fp16.h>
#include <math.h>
#include <stdint.h>

#define N_TOKENS 65536
#define EMB_DIM  128
#define NUM_EMB  1024

// Output tuple flattened scalar-wise in reference-return order:
// (e_latent_loss, quantized_st[N,D], perplexity, encodings[N,K])
#define OUT_LOSS 0
#define OUT_Q    1
#define OUT_PERP (1 + N_TOKENS * EMB_DIM)        // 8388609
#define OUT_ENC  (2 + N_TOKENS * EMB_DIM)        // 8388610 (even -> 8B-aligned)

#define BM   128
#define NBLK (N_TOKENS / BM)     // 512
#define CAP  32                  // candidate list capacity per token

#define APAD 68                  // A tile: half2 stride per k-row
#define BPAD 132                 // B tile: half2 stride per k-row (dup'd codes)
#define BBYTES (32 * BPAD * 4)   // 16896 per B buffer

// dynamic smem layout (bytes)
#define SM_A    0                // 34816 : A fp16 [k][tokenpair] half2
#define SM_B0   34816            // 16896 : B buffer 0
#define SM_B1   51712            // 16896 : B buffer 1
#define SM_SXP  68608            // 2048  : double sx partials[256]
#define SM_SXF  70656            // 512   : float sx[128]
#define SM_CNT  71168            // 512   : int scnt[128]
#define SM_LIST 71680            // 8192  : uint16 slist[128][CAP]
#define DSMEM   80896
// epilogue reuse inside SM_A (after screening):
#define SM2_SBK  0               // 512 : int bk[128]
#define SM2_LRED 512             // 2048: double lred[256]
#define SM2_LACC 2560            // 2048: double lacc[256]

__device__ __align__(16) __half g_ehalfT[EMB_DIM * NUM_EMB]; // [k][code], e*1024
__device__ float  g_be[NUM_EMB];     // fl32 of exact ||e_k||^2
__device__ int    g_hist[NUM_EMB];   // code counts
__device__ double g_lpart[NBLK];     // per-block loss partials
__device__ unsigned int g_done;      // last-block-done counter

__device__ __forceinline__ double wsumd(double v) {
#pragma unroll
    for (int o = 16; o > 0; o >>= 1) v += __shfl_down_sync(~0u, v, o);
    return v;   // valid on lane 0
}

// exact sequential-k fp32 dot (reference accumulation order), float4 loads
__device__ __forceinline__ float exact_dot(const float* __restrict__ xr,
                                           const float* __restrict__ er) {
    const float4* x4 = (const float4*)xr;
    const float4* e4 = (const float4*)er;
    float dot = 0.f;
#pragma unroll 4
    for (int q = 0; q < EMB_DIM / 4; q++) {
        float4 xv = x4[q], ev = e4[q];
        dot = __fmaf_rn(xv.x, ev.x, dot);
        dot = __fmaf_rn(xv.y, ev.y, dot);
        dot = __fmaf_rn(xv.z, ev.z, dot);
        dot = __fmaf_rn(xv.w, ev.w, dot);
    }
    return dot;
}

// ---------------------------------------------------------------------------
// prep: exact double code norms; transposed fp16 codebook scaled by 1024
// (keeps values out of fp16 subnormals); zero hist/done. Warp per code.
// ---------------------------------------------------------------------------
__global__ void vq_prep_kernel(const float* __restrict__ emb) {
    const int gtid = blockIdx.x * 256 + threadIdx.x;   // 32768 threads
    const int code = gtid >> 5, lane = gtid & 31;
    float4 v = ((const float4*)emb)[code * 32 + lane];
    double s;
    { double a = v.x, b = v.y, c = v.z, d = v.w; s = a*a + b*b + c*c + d*d; }
    float arr[4] = {v.x, v.y, v.z, v.w};
#pragma unroll
    for (int i = 0; i < 4; i++)
        g_ehalfT[(size_t)(lane * 4 + i) * NUM_EMB + code] =
            __float2half_rn(arr[i] * 1024.0f);
    s = wsumd(s);
    if (lane == 0) { g_be[code] = (float)s; g_hist[code] = 0; }
    if (gtid == 0) g_done = 0;
}

// ---------------------------------------------------------------------------
// main: fp16 HFMA2 screening GEMM with double-buffered B staging (register
// prefetch), half-warp shfl fold (no block syncs in the fold path), exact
// fp32 rescore (R3 bit-exact chain) + fused outputs.
// ---------------------------------------------------------------------------
__global__ __launch_bounds__(256, 2)
void vq_main_kernel(const float* __restrict__ x,
                    const float* __restrict__ emb,
                    float* __restrict__ out)
{
    extern __shared__ __align__(16) char dsm[];
    double*    sxp   = (double*)(dsm + SM_SXP);
    float*     sxf   = (float*)(dsm + SM_SXF);
    int*       scnt  = (int*)(dsm + SM_CNT);
    uint16_t*  slist = (uint16_t*)(dsm + SM_LIST);

    const int tid = threadIdx.x;          // 256
    const int tx  = tid & 15;             // codes tx + 16j (strided, cf-free)
    const int ty  = tid >> 4;             // token pairs ty*4 .. ty*4+3
    const int m0  = blockIdx.x * BM;

    // ---- zero this block's one-hot rows (big DRAM op, overlaps GEMM) ----
    {
        float2* enc2 = (float2*)(out + OUT_ENC);
        size_t base = (size_t)m0 * (NUM_EMB / 2);
        for (int i = tid; i < BM * NUM_EMB / 2; i += 256)
            enc2[base + i] = make_float2(0.f, 0.f);
    }

    // ---- A tile: x -> fp16 [k][tokenpair]; fused sx partials (double) ----
    {
        const int t = tid >> 1, kh = tid & 1;
        const float4* xr = (const float4*)(x + (size_t)(m0 + t) * EMB_DIM)
                           + kh * 16;
        const int pair = t >> 1, ln = t & 1;
        double sp = 0.0;
#pragma unroll 4
        for (int c = 0; c < 16; c++) {
            float4 v = xr[c];
            const int k = kh * 64 + c * 4;
            float arr[4] = {v.x, v.y, v.z, v.w};
#pragma unroll
            for (int i = 0; i < 4; i++)
                *(__half*)(dsm + SM_A + (size_t)((k + i) * APAD + pair) * 4
                           + ln * 2) = __float2half_rn(arr[i]);
            double a = v.x, b = v.y, cc = v.z, d = v.w;
            sp += a * a; sp += b * b; sp += cc * cc; sp += d * d;
        }
        sxp[tid] = sp;   // partial for token t, half kh (fixed pairing)
    }
    if (tid < 128) scnt[tid] = 0;
    __syncthreads();
    if (tid < 128) sxf[tid] = (float)(sxp[tid * 2] + sxp[tid * 2 + 1]);
    __syncthreads();

    // per-token running min / margin in registers (replicated over half-warp)
    float rmin[4][2], delta[4][2];
#pragma unroll
    for (int p = 0; p < 4; p++)
#pragma unroll
        for (int q = 0; q < 2; q++) {
            rmin[p][q]  = INFINITY;
            const float sx = sxf[ty * 8 + 2 * p + q];
            delta[p][q] = 2e-3f * fmaxf(1.0f, sqrtf(sx * 0.0078125f));
        }

    // ---- screening: 32 stages (ct = s>>2, ks = s&3), double-buffered B ----
    const int lr_c2 = tid & 63;           // staging: code pair
    const int lr_k0 = tid >> 6;           // staging: k base (0..3), step 4
    unsigned u[8];
    // prologue: prefetch stage 0
    {
        const __half* Esrc = g_ehalfT;    // ks=0, ct=0
#pragma unroll
        for (int r = 0; r < 8; r++)
            u[r] = *(const unsigned*)(Esrc
                + (size_t)(r * 4 + lr_k0) * NUM_EMB + lr_c2 * 2);
    }

    half2 acc[4][8];
    for (int s = 0; s < 32; s++) {
        char* buf = dsm + (s & 1 ? SM_B1 : SM_B0);
        // store prefetched chunk (dup'd) into this stage's buffer
#pragma unroll
        for (int r = 0; r < 8; r++) {
            const int k = r * 4 + lr_k0;
            half2 dlo = __half2half2(
                __ushort_as_half((unsigned short)(u[r] & 0xffffu)));
            half2 dhi = __half2half2(
                __ushort_as_half((unsigned short)(u[r] >> 16)));
            uint2 w; w.x = *(unsigned*)&dlo; w.y = *(unsigned*)&dhi;
            *(uint2*)(buf + (size_t)(k * BPAD + lr_c2 * 2) * 4) = w;
        }
        __syncthreads();

        // prefetch next stage (hidden behind compute)
        if (s < 31) {
            const int sn = s + 1;
            const __half* Esrc = g_ehalfT
                + (size_t)((sn & 3) * 32) * NUM_EMB + (sn >> 2) * 128;
#pragma unroll
            for (int r = 0; r < 8; r++)
                u[r] = *(const unsigned*)(Esrc
                    + (size_t)(r * 4 + lr_k0) * NUM_EMB + lr_c2 * 2);
        }

        if ((s & 3) == 0) {
#pragma unroll
            for (int p = 0; p < 4; p++)
#pragma unroll
                for (int j = 0; j < 8; j++)
                    acc[p][j] = __half2half2(
                        __ushort_as_half((unsigned short)0));
        }

        // HFMA2 inner loop over this 32-k chunk
#pragma unroll 4
        for (int k = 0; k < 32; k++) {
            const int kg = (s & 3) * 32 + k;
            uint4 av = *(const uint4*)(dsm + SM_A
                + (size_t)(kg * APAD + ty * 4) * 4);
            half2 a0 = *(half2*)&av.x, a1 = *(half2*)&av.y;
            half2 a2 = *(half2*)&av.z, a3 = *(half2*)&av.w;
            const half2* br = (const half2*)buf + k * BPAD;
#pragma unroll
            for (int j = 0; j < 8; j++) {
                half2 b = br[tx + 16 * j];        // conflict-free LDS.32
                acc[0][j] = __hfma2(a0, b, acc[0][j]);
                acc[1][j] = __hfma2(a1, b, acc[1][j]);
                acc[2][j] = __hfma2(a2, b, acc[2][j]);
                acc[3][j] = __hfma2(a3, b, acc[3][j]);
            }
        }

        // ---- end of ct: warp-local fold (no block sync) ----
        if ((s & 3) == 3) {
            const int ct = s >> 2;
            // per-thread tile-min per token
            float tmin[4][2];
#pragma unroll
            for (int p = 0; p < 4; p++) { tmin[p][0] = INFINITY; tmin[p][1] = INFINITY; }
#pragma unroll
            for (int j = 0; j < 8; j++) {
                const int kk = ct * 128 + tx + 16 * j;
                const float be = __ldg(&g_be[kk]);
#pragma unroll
                for (int p = 0; p < 4; p++) {
                    float2 df = __half22float2(acc[p][j]);
                    // s = be - 2*dot = be - (2/1024)*dot'  (exact pow2 scale)
                    tmin[p][0] = fminf(tmin[p][0],
                                       __fmaf_rn(-0.001953125f, df.x, be));
                    tmin[p][1] = fminf(tmin[p][1],
                                       __fmaf_rn(-0.001953125f, df.y, be));
                }
            }
            // butterfly min across the 16 owner lanes (order-independent)
#pragma unroll
            for (int m = 1; m <= 8; m <<= 1)
#pragma unroll
                for (int p = 0; p < 4; p++) {
                    tmin[p][0] = fminf(tmin[p][0],
                        __shfl_xor_sync(~0u, tmin[p][0], m));
                    tmin[p][1] = fminf(tmin[p][1],
                        __shfl_xor_sync(~0u, tmin[p][1], m));
                }
            // update running min; insert codes within margin of min-so-far
            float thr[4][2];
#pragma unroll
            for (int p = 0; p < 4; p++)
#pragma unroll
                for (int q = 0; q < 2; q++) {
                    rmin[p][q] = fminf(rmin[p][q], tmin[p][q]);
                    thr[p][q]  = rmin[p][q] + delta[p][q];
                }
#pragma unroll
            for (int j = 0; j < 8; j++) {
                const int kk = ct * 128 + tx + 16 * j;
                const float be = __ldg(&g_be[kk]);
#pragma unroll
                for (int p = 0; p < 4; p++) {
                    float2 df = __half22float2(acc[p][j]);
                    const int t0 = ty * 8 + 2 * p;
                    float s0 = __fmaf_rn(-0.001953125f, df.x, be);
                    float s1 = __fmaf_rn(-0.001953125f, df.y, be);
                    if (s0 <= thr[p][0]) {
                        int i = atomicAdd(scnt + t0, 1);
                        if (i < CAP) slist[t0 * CAP + i] = (uint16_t)kk;
                    }
                    if (s1 <= thr[p][1]) {
                        int i = atomicAdd(scnt + t0 + 1, 1);
                        if (i < CAP) slist[(t0 + 1) * CAP + i] = (uint16_t)kk;
                    }
                }
            }
        }
    }
    __syncthreads();   // lists complete; SM_A free for epilogue reuse

    // ---- phase 2: exact rescore (R3 bit-exact arithmetic) ----
    int*    s_bk = (int*)(dsm + SM2_SBK);
    double* lred = (double*)(dsm + SM2_LRED);
    double* lacc = (double*)(dsm + SM2_LACC);
    if (tid < 128) {
        const int row = m0 + tid;
        const float sxe = sxf[tid];
        const float* xr = x + (size_t)row * EMB_DIM;
        float bv = INFINITY;
        int   bk = 0;
        const int nc = scnt[tid];
        if (nc <= 0 || nc > CAP) {
            // safety fallback: full exact scan (nc>=1 is structural)
            for (int k = 0; k < NUM_EMB; k++) {
                float dot = exact_dot(xr, emb + (size_t)k * EMB_DIM);
                float d = __fsub_rn(__fadd_rn(sxe, g_be[k]),
                                    __fmul_rn(2.0f, dot));
                if (d < bv || (d == bv && k < bk)) { bv = d; bk = k; }
            }
        } else {
            bk = NUM_EMB - 1;
            // min over candidate set: order-independent -> deterministic
            for (int i = 0; i < nc; i++) {
                const int k = slist[tid * CAP + i];
                float dot = exact_dot(xr, emb + (size_t)k * EMB_DIM);
                float d = __fsub_rn(__fadd_rn(sxe, g_be[k]),
                                    __fmul_rn(2.0f, dot));
                if (d < bv || (d == bv && k < bk)) { bv = d; bk = k; }
            }
        }
        s_bk[tid] = bk;
        out[(size_t)OUT_ENC + (size_t)row * NUM_EMB + bk] = 1.0f;
        atomicAdd(&g_hist[bk], 1);   // integer atomic: deterministic
    }
    __syncthreads();

    // ---- cooperative coalesced quantized_st + loss (32-bit stores) ----
    double lsum = 0.0;
    float* oq = out + OUT_Q + (size_t)m0 * EMB_DIM;
    const float* xq = x + (size_t)m0 * EMB_DIM;
    for (int e = tid; e < BM * EMB_DIM; e += 256) {
        const int row = e >> 7;
        const int col = e & 127;
        const float xv = xq[e];
        const float qv = emb[(size_t)s_bk[row] * EMB_DIM + col];
        const float d  = __fsub_rn(qv, xv);
        oq[e] = __fadd_rn(xv, d);        // fl(x + fl(q-x)), exact STE math
        lsum += (double)d * (double)d;
    }
    lred[tid] = lsum;
    __syncthreads();
    for (int s = 128; s > 0; s >>= 1) {
        if (tid < s) lred[tid] += lred[tid + s];
        __syncthreads();
    }
    if (tid == 0) g_lpart[blockIdx.x] = lred[0];

    // ---- last block computes the scalars (fused finalize) ----
    __shared__ bool is_last;
    __threadfence();
    if (tid == 0) {
        unsigned v = atomicAdd(&g_done, 1u);
        is_last = (v == NBLK - 1);
    }
    __syncthreads();
    if (!is_last) return;

    double ent = 0.0;
#pragma unroll
    for (int b = 0; b < 4; b++) {
        double pr = (double)g_hist[tid * 4 + b] / (double)N_TOKENS;
        ent += pr * log(pr + 1e-10);
    }
    double ls = 0.0;
#pragma unroll
    for (int b = 0; b < 2; b++) ls += g_lpart[tid * 2 + b];
    lred[tid] = ent;
    lacc[tid] = ls;
    __syncthreads();
    for (int s = 128; s > 0; s >>= 1) {
        if (tid < s) { lred[tid] += lred[tid + s]; lacc[tid] += lacc[tid + s]; }
        __syncthreads();
    }
    if (tid == 0) {
        out[OUT_PERP] = (float)exp(-lred[0]);
        out[OUT_LOSS] = (float)(lacc[0] / ((double)N_TOKENS * (double)EMB_DIM));
    }
}

// ---------------------------------------------------------------------------
extern "C" void kernel_launch(void* const* d_in, const int* in_sizes, int n_in,
                              void* d_out, int out_size) {
    const float* x   = (const float*)d_in[0];   // inputs [65536,128]
    const float* emb = (const float*)d_in[1];   // emb_w  [1024,128]
    float* out = (float*)d_out;

    cudaFuncSetAttribute(vq_main_kernel,
                         cudaFuncAttributeMaxDynamicSharedMemorySize, DSMEM);
    vq_prep_kernel<<<NUM_EMB * 32 / 256, 256>>>(emb);
    vq_main_kernel<<<NBLK, 256, DSMEM>>>(x, emb, out);
}